// round 16
// baseline (speedup 1.0000x reference)
#include <cuda_runtime.h>
#include <cstdint>

#define N_B   32
#define E_DIM 1024
#define IN_DIM 300
#define D_DIM 128
#define NTYPE 3
#define NEG_INF (-9e15f)

// ---------------- persistent device scratch ----------------
__device__ float d_vL[NTYPE][N_B][IN_DIM];
__device__ float d_vR[NTYPE][N_B][IN_DIM];
__device__ float d_Lrow[NTYPE][N_B][E_DIM];
__device__ float d_Rrow[NTYPE][N_B][E_DIM];
__device__ __align__(16) float2 d_h2dup[N_B][E_DIM][D_DIM]; // H duplicated (32 MB)
__device__ __align__(16) float d_P[N_B][E_DIM][E_DIM];      // softmax probs (134 MB)
__device__ int d_adj_is64;

// ---------------- helpers ----------------
__device__ __forceinline__ uint32_t smem_u32(const void* p) {
    uint32_t a;
    asm("{ .reg .u64 t; cvta.to.shared.u64 t, %1; cvt.u32.u64 %0, t; }" : "=r"(a) : "l"(p));
    return a;
}
#define CP_ASYNC16(dst, src) \
    asm volatile("cp.async.cg.shared.global [%0], [%1], 16;" :: "r"(dst), "l"(src) : "memory")
#define CP_COMMIT() asm volatile("cp.async.commit_group;" ::: "memory")
#define CP_WAIT0()  asm volatile("cp.async.wait_group 0;" ::: "memory")

// ---------------- K0: adj dtype probe ----------------
__global__ __launch_bounds__(256) void k0_detect(const unsigned int* __restrict__ w)
{
    __shared__ unsigned int r[256];
    unsigned int v = 0;
    for (int i = threadIdx.x; i < 4096; i += 256) v |= w[2 * i + 1];
    r[threadIdx.x] = v;
    __syncthreads();
    for (int s = 128; s; s >>= 1) {
        if (threadIdx.x < s) r[threadIdx.x] |= r[threadIdx.x + s];
        __syncthreads();
    }
    if (threadIdx.x == 0) d_adj_is64 = (r[0] == 0u) ? 1 : 0;
}

// ---------------- K1: gates + projected attention vectors ----------------
__global__ __launch_bounds__(256) void k1_gates(
    const float* __restrict__ q, const float* __restrict__ W,
    const float* __restrict__ a, const float* __restrict__ qW1,
    const float* __restrict__ qW2)
{
    int t = blockIdx.x;
    int n = blockIdx.y;
    int tid = threadIdx.x;
    __shared__ float qs[IN_DIM];
    __shared__ float r1[256];
    __shared__ float ga[256];

    for (int k = tid; k < IN_DIM; k += 256) qs[k] = q[n * IN_DIM + k];
    __syncthreads();
    {
        float acc = 0.f;
        const float* w = qW1 + (size_t)t * IN_DIM * 256 + tid;
        #pragma unroll 4
        for (int k = 0; k < IN_DIM; k++) acc += qs[k] * w[(size_t)k * 256];
        r1[tid] = fmaxf(acc, 0.f);
    }
    __syncthreads();
    {
        float acc = 0.f;
        const float* w = qW2 + (size_t)t * 256 * 256 + tid;
        #pragma unroll 4
        for (int k = 0; k < 256; k++) acc += r1[k] * w[(size_t)k * 256];
        float g = 1.f / (1.f + __expf(-acc));
        ga[tid] = g * a[t * 256 + tid];
    }
    __syncthreads();
    for (int k = tid; k < IN_DIM; k += 256) {
        const float* w = W + ((size_t)t * IN_DIM + k) * D_DIM;
        float aL = 0.f, aR = 0.f;
        #pragma unroll 4
        for (int dd = 0; dd < D_DIM; dd++) {
            float wv = w[dd];
            aL += wv * ga[dd];
            aR += wv * ga[128 + dd];
        }
        d_vL[t][n][k] = aL;
        d_vR[t][n][k] = aR;
    }
}

// ---------------- K2a: left/right tables ----------------
__global__ __launch_bounds__(256) void k2a_leftright(const float* __restrict__ x)
{
    int gw = (blockIdx.x * 256 + threadIdx.x) >> 5;
    int lane = threadIdx.x & 31;
    int n = gw >> 10;
    int e = gw & 1023;
    const float* row = x + (size_t)(n * E_DIM + e) * IN_DIM;
    float s0 = 0.f, s1 = 0.f, s2 = 0.f, s3 = 0.f, s4 = 0.f, s5 = 0.f;
    for (int k = lane; k < IN_DIM; k += 32) {
        float xv = row[k];
        s0 += xv * d_vL[0][n][k];  s1 += xv * d_vR[0][n][k];
        s2 += xv * d_vL[1][n][k];  s3 += xv * d_vR[1][n][k];
        s4 += xv * d_vL[2][n][k];  s5 += xv * d_vR[2][n][k];
    }
    #pragma unroll
    for (int o = 16; o; o >>= 1) {
        s0 += __shfl_xor_sync(0xffffffffu, s0, o);
        s1 += __shfl_xor_sync(0xffffffffu, s1, o);
        s2 += __shfl_xor_sync(0xffffffffu, s2, o);
        s3 += __shfl_xor_sync(0xffffffffu, s3, o);
        s4 += __shfl_xor_sync(0xffffffffu, s4, o);
        s5 += __shfl_xor_sync(0xffffffffu, s5, o);
    }
    if (lane == 0) {
        d_Lrow[0][n][e] = s0;  d_Rrow[0][n][e] = s1;
        d_Lrow[1][n][e] = s2;  d_Rrow[1][n][e] = s3;
        d_Lrow[2][n][e] = s4;  d_Rrow[2][n][e] = s5;
    }
}

// ---------------- K3: single-pass softmax -> P (f32) ----------------
__global__ __launch_bounds__(256) void k3_softmax(const void* __restrict__ adjv)
{
    int n = blockIdx.y;
    int i = blockIdx.x * 8 + (threadIdx.x >> 5);
    int lane = threadIdx.x & 31;
    int tid = threadIdx.x;
    int is64 = d_adj_is64;

    __shared__ float Rs[4][E_DIM];   // row 3 = zero pad (safe OOB target)
    for (int idx = tid; idx < 4 * E_DIM; idx += 256) {
        int t = idx >> 10, j = idx & 1023;
        Rs[t][j] = (t < 3) ? d_Rrow[t][n][j] : 0.f;
    }
    __syncthreads();

    float L0 = d_Lrow[0][n][i], L1 = d_Lrow[1][n][i], L2 = d_Lrow[2][n][i];
    size_t rowoff = ((size_t)(n * E_DIM + i)) << 10;
    const int* arow32 = (const int*)adjv + rowoff;
    const long long* arow64 = (const long long*)adjv + rowoff;

    float e[8][4];
    float sum = 0.f;
    #pragma unroll
    for (int m = 0; m < 8; m++) {
        int j0 = m * 128 + lane * 4;
        int av[4];
        if (!is64) {
            int4 v = *reinterpret_cast<const int4*>(&arow32[j0]);
            av[0] = v.x; av[1] = v.y; av[2] = v.z; av[3] = v.w;
        } else {
            av[0] = (int)arow64[j0];     av[1] = (int)arow64[j0 + 1];
            av[2] = (int)arow64[j0 + 2]; av[3] = (int)arow64[j0 + 3];
        }
        #pragma unroll
        for (int b = 0; b < 4; b++) {
            int a = av[b];
            float Lt = (a == 1) ? L0 : ((a == 2) ? L1 : L2);
            float Rt = Rs[(a - 1) & 3][j0 + b];
            float v = Lt + Rt;
            float lv = fmaxf(v, 0.2f * v);
            float ev = (a > 0) ? __expf(lv) : 0.f;
            e[m][b] = ev;
            sum += ev;
        }
    }
    #pragma unroll
    for (int o = 16; o; o >>= 1) sum += __shfl_xor_sync(0xffffffffu, sum, o);
    float rinv = 1.f / sum;
    #pragma unroll
    for (int m = 0; m < 8; m++) {
        int j0 = m * 128 + lane * 4;
        float4 pv = make_float4(e[m][0] * rinv, e[m][1] * rinv,
                                e[m][2] * rinv, e[m][3] * rinv);
        *reinterpret_cast<float4*>(&d_P[n][i][j0]) = pv;
    }
}

// ---------------- K2b: h2 = x @ W[2]; emit H duplicated (float2) ----------------
#define BK2 20
#define K2B_PS 132
#define K2B_HS 136
__global__ __launch_bounds__(256, 2) void k2b_h2(
    const float* __restrict__ x, const float* __restrict__ W)
{
    __shared__ float2 As2[BK2][K2B_PS];
    __shared__ float  Bs[BK2][K2B_HS];

    int n = blockIdx.y;
    int e0 = blockIdx.x * 128;
    const float* W2 = W + (size_t)2 * IN_DIM * D_DIM;
    int tid = threadIdx.x;
    int tx = tid & 15, ty = tid >> 4;
    int le = tid >> 1;
    int lk = (tid & 1) * 10;

    unsigned long long acc[8][4];
    #pragma unroll
    for (int j = 0; j < 8; j++)
        #pragma unroll
        for (int p = 0; p < 4; p++) acc[j][p] = 0ull;

    for (int k0 = 0; k0 < IN_DIM; k0 += BK2) {
        __syncthreads();
        {
            const float* xr = x + ((size_t)(n * E_DIM + e0 + le) * IN_DIM + k0 + lk);
            #pragma unroll
            for (int u = 0; u < 10; u++) {
                float v = xr[u];
                As2[lk + u][le] = make_float2(v, v);
            }
        }
        #pragma unroll
        for (int u = 0; u < 10; u++) {
            int idx = tid + 256 * u;
            int k = idx >> 7, dd = idx & 127;
            Bs[k][dd] = W2[(size_t)(k0 + k) * D_DIM + dd];
        }
        __syncthreads();
        #pragma unroll 5
        for (int k = 0; k < BK2; k++) {
            unsigned long long af[8];
            const ulonglong2* ap =
                reinterpret_cast<const ulonglong2*>(&As2[k][ty * 8]);
            #pragma unroll
            for (int q = 0; q < 4; q++) { ulonglong2 v = ap[q]; af[2*q] = v.x; af[2*q+1] = v.y; }
            unsigned long long bf[4];
            #pragma unroll
            for (int p = 0; p < 4; p++)
                bf[p] = *reinterpret_cast<const unsigned long long*>(&Bs[k][32 * p + 2 * tx]);
            #pragma unroll
            for (int j = 0; j < 8; j++)
                #pragma unroll
                for (int p = 0; p < 4; p++)
                    asm("fma.rn.f32x2 %0, %1, %2, %0;"
                        : "+l"(acc[j][p]) : "l"(af[j]), "l"(bf[p]));
        }
    }
    // epilogue: duplicated stores. acc[j][p]: e = e0+ty*8+j, d = 32p+2tx+{0,1}
    #pragma unroll
    for (int j = 0; j < 8; j++) {
        float2* row = &d_h2dup[n][e0 + ty * 8 + j][0];
        #pragma unroll
        for (int p = 0; p < 4; p++) {
            unsigned int lo, hi;
            asm("mov.b64 {%0, %1}, %2;" : "=r"(lo), "=r"(hi) : "l"(acc[j][p]));
            float vlo = __uint_as_float(lo), vhi = __uint_as_float(hi);
            *reinterpret_cast<float4*>(row + 32 * p + 2 * tx) =
                make_float4(vlo, vlo, vhi, vhi);
        }
    }
}

// ---------------- K4: out[n] = P^T @ H  -------------------------------
// 256 threads, 128j x 64d tile, grid (16,32), 3 CTAs/SM (6 warps/SMSP).
// f32x2 packs j: A = vector P-pairs (LDS.128), B = pre-dup'd H (LDS.128).
// Per k-step: 4 LDS.128 + 16 FFMA2 = 20 issues / 32 fma-pipe cycles.
#define K4_CH 64
#define K4_PS 132                               // P row stride (floats)
#define K4_HS 66                                // Hdup row stride (float2)
#define K4_PBYTES (K4_CH * K4_PS * 4)           // 33792
#define K4_SMEM   (K4_PBYTES + K4_CH * K4_HS * 8)   // 67584
__global__ __launch_bounds__(256, 3) void k4_pv(float* __restrict__ out)
{
    extern __shared__ char smemraw[];
    float*  Ps = reinterpret_cast<float*>(smemraw);
    float2* Hd = reinterpret_cast<float2*>(smemraw + K4_PBYTES);
    uint32_t psb = smem_u32(Ps), hdb = smem_u32(Hd);

    int n = blockIdx.y;
    int j0 = (blockIdx.x & 7) * 128;
    int d0 = (blockIdx.x >> 3) * 64;
    int tid = threadIdx.x;
    int tx = tid & 15, ty = tid >> 4;   // ty: j-group (8 j), tx: d-group (4 d)

    unsigned long long acc[4][4];
    #pragma unroll
    for (int jp = 0; jp < 4; jp++)
        #pragma unroll
        for (int dd = 0; dd < 4; dd++) acc[jp][dd] = 0ull;

    for (int it = 0; it < 16; it++) {
        int i0 = it * K4_CH;
        __syncthreads();                 // previous chunk's readers done
        #pragma unroll
        for (int c = 0; c < 8; c++) {
            int f4 = tid + 256 * c;      // 0..2047
            int row = f4 >> 5, c32 = f4 & 31;
            // P: row i, 128 floats (32 float4)
            CP_ASYNC16(psb + (uint32_t)(row * K4_PS + c32 * 4) * 4u,
                       &d_P[n][i0 + row][j0 + c32 * 4]);
            // Hdup: row i, 64 float2 (32 float4)
            CP_ASYNC16(hdb + (uint32_t)(row * K4_HS + c32 * 2) * 8u,
                       &d_h2dup[n][i0 + row][d0 + c32 * 2]);
        }
        CP_COMMIT();
        CP_WAIT0();
        __syncthreads();                 // tiles visible
        #pragma unroll 4
        for (int k = 0; k < K4_CH; k++) {
            unsigned long long aa[4];
            {
                const ulonglong2* ap =
                    reinterpret_cast<const ulonglong2*>(&Ps[k * K4_PS + ty * 8]);
                ulonglong2 v0 = ap[0], v1 = ap[1];
                aa[0] = v0.x; aa[1] = v0.y; aa[2] = v1.x; aa[3] = v1.y;
            }
            unsigned long long bb[4];
            {
                const ulonglong2* bp =
                    reinterpret_cast<const ulonglong2*>(&Hd[k * K4_HS + tx * 4]);
                ulonglong2 v0 = bp[0], v1 = bp[1];
                bb[0] = v0.x; bb[1] = v0.y; bb[2] = v1.x; bb[3] = v1.y;
            }
            #pragma unroll
            for (int jp = 0; jp < 4; jp++)
                #pragma unroll
                for (int dd = 0; dd < 4; dd++)
                    asm("fma.rn.f32x2 %0, %1, %2, %0;"
                        : "+l"(acc[jp][dd]) : "l"(aa[jp]), "l"(bb[dd]));
        }
    }
    // epilogue: acc[jp][dd] = (out[j0+ty*8+2jp][d], out[..+2jp+1][d]), d = d0+tx*4+dd
    #pragma unroll
    for (int jp = 0; jp < 4; jp++) {
        unsigned int lo[4], hi[4];
        #pragma unroll
        for (int dd = 0; dd < 4; dd++)
            asm("mov.b64 {%0, %1}, %2;" : "=r"(lo[dd]), "=r"(hi[dd]) : "l"(acc[jp][dd]));
        int jrow = j0 + ty * 8 + 2 * jp;
        float* o0 = out + ((size_t)n * E_DIM + jrow) * D_DIM + d0 + tx * 4;
        float* o1 = o0 + D_DIM;
        *reinterpret_cast<float4*>(o0) =
            make_float4(__uint_as_float(lo[0]), __uint_as_float(lo[1]),
                        __uint_as_float(lo[2]), __uint_as_float(lo[3]));
        *reinterpret_cast<float4*>(o1) =
            make_float4(__uint_as_float(hi[0]), __uint_as_float(hi[1]),
                        __uint_as_float(hi[2]), __uint_as_float(hi[3]));
    }
}

// ---------------- launch ----------------
extern "C" void kernel_launch(void* const* d_in, const int* in_sizes, int n_in,
                              void* d_out, int out_size)
{
    const float*  input_state = (const float*)d_in[0];
    const void*   adj         = (const void*)d_in[1];
    const float*  query_vec   = (const float*)d_in[3];
    const float*  W           = (const float*)d_in[4];
    const float*  a           = (const float*)d_in[5];
    const float*  qW1         = (const float*)d_in[6];
    const float*  qW2         = (const float*)d_in[7];
    float* out = (float*)d_out;
    (void)in_sizes; (void)n_in; (void)out_size;

    cudaFuncSetAttribute(k4_pv, cudaFuncAttributeMaxDynamicSharedMemorySize, K4_SMEM);

    k0_detect<<<1, 256>>>((const unsigned int*)adj);
    k1_gates<<<dim3(NTYPE, N_B), 256>>>(query_vec, W, a, qW1, qW2);
    k2a_leftright<<<(N_B * E_DIM) / 8, 256>>>(input_state);
    k3_softmax<<<dim3(128, N_B), 256>>>(adj);
    k2b_h2<<<dim3(8, N_B), 256>>>(input_state, W);
    k4_pv<<<dim3(16, N_B), 256, K4_SMEM>>>(out);
}